// round 17
// baseline (speedup 1.0000x reference)
#include <cuda_runtime.h>
#include <cuda_bf16.h>

#define HH 320
#define WW 320
#define KS 31
#define PADK 15
#define HOUT 289        // 320 - 16 - 15
#define NCOMBO 3600     // 180 thetas x 20 freqs
#define KROW 32         // padded kernel row (31 + 1 zero)
#define KSTRIDE (KS * KROW)   // 992 floats per combo = 31 x 128B lines

#define PXB 16          // pixel columns per block (two per warp)
#define NWARP 8
#define RPB 4           // output rows per block
#define SMR4 34         // smem rows: 31 + 3 (covers four output rows)
#define SMC 48          // smem cols (46 used, padded)
#define GX 19           // ceil(289/16)
#define GYC 73          // ceil(289/4) conv block-rows
#define NBORDER 18879   // 320^2 - 289^2

// Precomputed Gabor kernel table: [3600][31*32] floats = 14.27 MB (L2-resident).
__device__ __align__(16) float g_ker[NCOMBO * KSTRIDE];
// Scratch for global min/max (monotonic-uint encoded floats).
__device__ unsigned g_mm[2];

__device__ __forceinline__ unsigned encf(float f) {
    unsigned u = __float_as_uint(f);
    return (u & 0x80000000u) ? ~u : (u | 0x80000000u);
}
__device__ __forceinline__ float decf(unsigned u) {
    return (u & 0x80000000u) ? __uint_as_float(u ^ 0x80000000u)
                             : __uint_as_float(~u);
}

// Fill the kernel table (validated Chebyshev form, unchanged from R11/R16).
// grid = (180, 2, 2), block = 128.
__global__ __launch_bounds__(128) void k_fill()
{
    __shared__ float s_st, s_ct;
    if (threadIdx.x == 0) {
        if (blockIdx.x == 0 && blockIdx.y == 0 && blockIdx.z == 0) {
            g_mm[0] = 0xFFFFFFFFu;  // min identity (encoded)
            g_mm[1] = 0u;           // max identity
        }
        const float th = (float)blockIdx.x / 180.0f * 3.14159265358979323846f;
        float st, ct;
        sincosf(th, &st, &ct);      // precise — same values as validated kernel
        s_st = st; s_ct = ct;
    }
    __syncthreads();

    const int t    = blockIdx.x;
    const int qi   = threadIdx.x;
    const int row  = blockIdx.y * 16 + (qi >> 3);   // 8 quads per row
    const int f0i  = blockIdx.z * 10;

    if (row < KS) {
        const float st = s_st, ct = s_ct;
        const int qcol = (qi & 7) * 4;
        const float y = (float)(row - PADK);
        const float yst = y * st;
        const float yct = y * ct;

        float env[4], c0[4], c1[4], k2[4];
        #pragma unroll
        for (int j = 0; j < 4; ++j) {
            const int b = qcol + j;                  // col 0..31 (31 = pad)
            const float x  = (float)(b - PADK);
            const float xt = fmaf(x, ct, yst);
            const float yt = fmaf(-x, st, yct);
            const float ga = fmaf(0.04f, fabsf(yt), 1.0f);
            const float gy = ga * yt;
            const float q  = fmaf(gy, gy, xt * xt);
            env[j] = (b < KS) ? __expf(q * (-1.0f / 72.0f)) : 0.0f;
            const float C  = xt * fmaf(yt, 1.0f / 45.0f, 1.0f);  // xt*(1+yt/45)
            const float d  = (6.283185307179586f * 0.0015f) * C;
            const float a0 = fmaf((float)f0i, d, (6.283185307179586f * 0.025f) * C);
            c1[j] = __cosf(a0);          // T(0)  at fi = f0i
            c0[j] = __cosf(a0 - d);      // T(-1)
            k2[j] = 2.0f * __cosf(d);
        }

        float* dst = &g_ker[(t * 20 + f0i) * KSTRIDE + row * KROW + qcol];
        #pragma unroll
        for (int fi = 0; fi < 10; ++fi) {
            float4 wv;
            wv.x = env[0] * c1[0];
            wv.y = env[1] * c1[1];
            wv.z = env[2] * c1[2];
            wv.w = env[3] * c1[3];
            *reinterpret_cast<float4*>(dst + fi * KSTRIDE) = wv;
            #pragma unroll
            for (int j = 0; j < 4; ++j) {
                const float tn = fmaf(k2[j], c1[j], -c0[j]);
                c0[j] = c1[j]; c1[j] = tn;
            }
        }
    }
#if __CUDA_ARCH__ >= 900
    cudaTriggerProgrammaticLaunchCompletion();
#endif
}

// Convolution + border min/max. gridDim = (GX, GYC + 4), block = 256.
// Conv blocks process FOUR output rows sharing one 34x48 patch: per warp
// 2 cols x 4 rows = 8 pixels / 8 independent accumulator+LDG streams.
// Per-pixel FP accumulation order identical to the validated kernel.
__global__ __launch_bounds__(256) void k_conv(
    const float* __restrict__ fp,
    const int*   __restrict__ fmap,
    const int*   __restrict__ tmap,
    float* __restrict__ out)
{
    __shared__ float sm[SMR4 * SMC];
    __shared__ unsigned swmin[NWARP], swmax[NWARP];

    const int tid  = threadIdx.x;
    const int lane = tid & 31;
    const int w    = tid >> 5;
    const int by   = blockIdx.y;

    if (by < GYC) {
        const int oy0 = RPB * by;
        const int ox0 = blockIdx.x * PXB;

        // Pixel columns for this warp.
        const int p0 = 2 * w, p1 = 2 * w + 1;
        const int ox0p = ox0 + p0, ox1p = ox0 + p1;
        const bool vx0 = (ox0p < HOUT), vx1 = (ox1p < HOUT);
        const int SAFE = PADK * WW + PADK;

        bool vv[8];         // [row r][col c] -> index 2r+c
        int  ci[8];
        int  cb[8];
        #pragma unroll
        for (int r = 0; r < RPB; ++r) {
            const bool vr = (oy0 + r < HOUT);
            const int rowbase = (oy0 + r + PADK) * WW + PADK;
            vv[2*r]   = vx0 && vr;
            vv[2*r+1] = vx1 && vr;
            ci[2*r]   = rowbase + ox0p;
            ci[2*r+1] = rowbase + ox1p;
            const int s0 = vv[2*r]   ? ci[2*r]   : SAFE;
            const int s1 = vv[2*r+1] ? ci[2*r+1] : SAFE;
            cb[2*r]   = tmap[s0] * 20 + fmap[s0];
            cb[2*r+1] = tmap[s1] * 20 + fmap[s1];
        }

        // Load patch rows oy0..oy0+33, cols ox0..ox0+47 (zero-fill OOB).
        for (int i = tid; i < SMR4 * SMC; i += 256) {
            const int r = i / SMC, c = i % SMC;
            const int gy = oy0 + r, gx = ox0 + c;
            sm[i] = (gy < HH && gx < WW) ? fp[gy * WW + gx] : 0.0f;
        }
        __syncthreads();

#if __CUDA_ARCH__ >= 900
        cudaGridDependencySynchronize();   // wait for k_fill's g_ker/g_mm
#endif
        const float* kr[8];
        #pragma unroll
        for (int q = 0; q < 8; ++q) kr[q] = &g_ker[cb[q] * KSTRIDE];

        float acc[8];
        #pragma unroll
        for (int q = 0; q < 8; ++q) acc[q] = 0.0f;

        const float* __restrict__ pr0 = &sm[p0 + lane];
        #pragma unroll
        for (int a = 0; a < KS; ++a) {
            float wv[8], pv[8];
            #pragma unroll
            for (int q = 0; q < 8; ++q)
                wv[q] = kr[q][a * KROW + lane];      // 8 coalesced 128B lines
            #pragma unroll
            for (int r = 0; r < RPB; ++r) {
                pv[2*r]   = pr0[(a + r) * SMC];      // conflict-free LDS
                pv[2*r+1] = pr0[(a + r) * SMC + 1];
            }
            #pragma unroll
            for (int q = 0; q < 8; ++q)
                acc[q] = fmaf(pv[q], wv[q], acc[q]);
        }
        #pragma unroll
        for (int off = 16; off > 0; off >>= 1) {
            #pragma unroll
            for (int q = 0; q < 8; ++q)
                acc[q] += __shfl_down_sync(0xFFFFFFFFu, acc[q], off);
        }

        if (lane == 0) {
            unsigned m = 0xFFFFFFFFu, M = 0u;
            #pragma unroll
            for (int q = 0; q < 8; ++q) {
                if (vv[q]) {
                    out[ci[q]] = acc[q];
                    const unsigned e = encf(acc[q]);
                    m = min(m, e); M = max(M, e);
                }
            }
            swmin[w] = m;
            swmax[w] = M;
        }
        __syncthreads();
        if (tid == 0) {
            unsigned m = 0xFFFFFFFFu, M = 0u;
            #pragma unroll
            for (int i = 0; i < NWARP; ++i) { m = min(m, swmin[i]); M = max(M, swmax[i]); }
            atomicMin(&g_mm[0], m);
            atomicMax(&g_mm[1], M);
        }
    } else {
        // Border min/max: 4 rows x GX blocks x 256 threads = 19456 >= 18879.
        const int k = ((by - GYC) * GX + blockIdx.x) * 256 + tid;
        unsigned km = 0xFFFFFFFFu, kM = 0u;
        if (k < NBORDER) {
            int row, col;
            if (k < 31 * WW) {                // full border rows: 0..14, 304..319
                const int r = k / WW;
                row = (r < PADK) ? r : r + HOUT;
                col = k % WW;
            } else {                          // side cols of interior rows
                const int k2 = k - 31 * WW;
                row = PADK + k2 / 31;
                const int c = k2 % 31;
                col = (c < PADK) ? c : c + HOUT;
            }
            const float v = fp[row * WW + col];
            km = kM = encf(v);
        }
        km = __reduce_min_sync(0xFFFFFFFFu, km);
        kM = __reduce_max_sync(0xFFFFFFFFu, kM);
        if (lane == 0) { swmin[w] = km; swmax[w] = kM; }
        __syncthreads();
#if __CUDA_ARCH__ >= 900
        cudaGridDependencySynchronize();   // g_mm init lives in k_fill
#endif
        if (tid == 0) {
            unsigned m = 0xFFFFFFFFu, M = 0u;
            #pragma unroll
            for (int i = 0; i < NWARP; ++i) { m = min(m, swmin[i]); M = max(M, swmax[i]); }
            atomicMin(&g_mm[0], m);
            atomicMax(&g_mm[1], M);
        }
    }
}

// Vectorized threshold. PDL: fp loads (input) before the dependency sync.
__global__ __launch_bounds__(256) void k_thresh(
    const float* __restrict__ fp, float* __restrict__ out)
{
    const int idx4 = blockIdx.x * 256 + threadIdx.x;
    if (idx4 >= (HH * WW) / 4) return;
    const int base = idx4 * 4;
    const int i = base / WW;
    const int j0 = base % WW;
    const bool rowin = (i >= PADK) && (i < PADK + HOUT);

    float4 fv = ((const float4*)fp)[idx4];     // input read — overlaps conv tail

#if __CUDA_ARCH__ >= 900
    cudaGridDependencySynchronize();           // wait for conv's out + g_mm
#endif
    const float mn  = decf(g_mm[0]);
    const float mxv = decf(g_mm[1]) - mn;      // max of (out - min)
    const float s   = (mxv != 0.0f) ? (100.0f / mxv) : 1.0f;

    float4 ov = ((const float4*)out)[idx4];
    float r[4] = {ov.x, ov.y, ov.z, ov.w};
    float f[4] = {fv.x, fv.y, fv.z, fv.w};
    #pragma unroll
    for (int c = 0; c < 4; ++c) {
        const int j = j0 + c;
        const bool inter = rowin && (j >= PADK) && (j < PADK + HOUT);
        const float src = inter ? r[c] : f[c];
        const float t = (src - mn) * s;
        r[c] = (t > 55.0f) ? 100.0f : 0.0f;
    }
    ((float4*)out)[idx4] = make_float4(r[0], r[1], r[2], r[3]);
}

extern "C" void kernel_launch(void* const* d_in, const int* in_sizes, int n_in,
                              void* d_out, int out_size)
{
    const float* fp   = (const float*)d_in[0];   // fprint
    const int*   fmap = (const int*)d_in[1];     // freq_map
    const int*   tmap = (const int*)d_in[2];     // theta_map
    float* out = (float*)d_out;

    dim3 fgrid(180, 2, 2);
    k_fill<<<fgrid, 128>>>();

    cudaLaunchAttribute pdl[1];
    pdl[0].id = cudaLaunchAttributeProgrammaticStreamSerialization;
    pdl[0].val.programmaticStreamSerializationAllowed = 1;

    {
        cudaLaunchConfig_t cfg = {};
        cfg.gridDim = dim3(GX, GYC + 4);         // 19 x 77
        cfg.blockDim = dim3(256);
        cfg.dynamicSmemBytes = 0;
        cfg.stream = 0;
        cfg.attrs = pdl;
        cfg.numAttrs = 1;
        cudaLaunchKernelEx(&cfg, k_conv, fp, fmap, tmap, out);
    }
    {
        cudaLaunchConfig_t cfg = {};
        cfg.gridDim = dim3((HH * WW / 4 + 255) / 256);
        cfg.blockDim = dim3(256);
        cfg.dynamicSmemBytes = 0;
        cfg.stream = 0;
        cfg.attrs = pdl;
        cfg.numAttrs = 1;
        cudaLaunchKernelEx(&cfg, k_thresh, fp, out);
    }
}